// round 5
// baseline (speedup 1.0000x reference)
#include <cuda_runtime.h>

#define NROWS 8192
#define DIM   128
#define BT    128      // output tile (BT x BT)
#define THREADS 256

// ---------------- device scratch (no allocs allowed) ----------------
__device__ float g_sq[NROWS];
__device__ int   g_pos[NROWS];   // float bits, running max (hardest positive)
__device__ int   g_neg[NROWS];   // float bits, running min (hardest negative)

// ---------------- prep: squared norms + init reductions ----------------
__global__ void prep_kernel(const float* __restrict__ X) {
    int i = blockIdx.x * blockDim.x + threadIdx.x;
    if (i >= NROWS) return;
    const float4* row = (const float4*)(X + (size_t)i * DIM);
    float s = 0.f;
#pragma unroll
    for (int q = 0; q < DIM / 4; q++) {
        float4 v = row[q];
        s += v.x * v.x + v.y * v.y + v.z * v.z + v.w * v.w;
    }
    g_sq[i]  = s;
    g_pos[i] = 0;            // 0.0f
    g_neg[i] = 0x7F7FFFFF;   // FLT_MAX
}

// ---------------- main: tiled Gram + fused hardest-pos/neg ----------------
__global__ void tile_kernel(const float* __restrict__ X,
                            const int* __restrict__ labels) {   // int32: JAX x64 is off,
                                                                // int64 request silently
                                                                // materializes as int32
    extern __shared__ float smem[];
    float* As = smem;                 // k-major: As[k*129 + i_local]
    float* Bs = smem + 128 * 129;     // k-major: Bs[k*129 + j_local]
    __shared__ int   labA[BT];
    __shared__ int   labB[BT];
    __shared__ float sqB[BT];

    const int tid = threadIdx.x;
    const int tx  = tid & 15;
    const int ty  = tid >> 4;
    const int ib  = blockIdx.y * BT;
    const int jb  = blockIdx.x * BT;

    // Load both tiles, transposing to k-major. Global side is coalesced
    // (each group of 32 lanes reads one 512B row). SMEM store has bounded
    // conflicts (one-time cost, amortized over the 128-deep k loop).
    for (int t = tid; t < BT * (DIM / 4); t += THREADS) {
        int kq  = t & 31;          // float4 index along k
        int row = t >> 5;
        float4 va = *(const float4*)(X + (size_t)(ib + row) * DIM + kq * 4);
        float4 vb = *(const float4*)(X + (size_t)(jb + row) * DIM + kq * 4);
        int k0 = kq * 4;
        As[(k0 + 0) * 129 + row] = va.x;
        As[(k0 + 1) * 129 + row] = va.y;
        As[(k0 + 2) * 129 + row] = va.z;
        As[(k0 + 3) * 129 + row] = va.w;
        Bs[(k0 + 0) * 129 + row] = vb.x;
        Bs[(k0 + 1) * 129 + row] = vb.y;
        Bs[(k0 + 2) * 129 + row] = vb.z;
        Bs[(k0 + 3) * 129 + row] = vb.w;
    }
    if (tid < BT) {
        labA[tid] = labels[ib + tid];
        labB[tid] = labels[jb + tid];
        sqB[tid]  = g_sq[jb + tid];
    }
    __syncthreads();

    float acc[8][8];
#pragma unroll
    for (int r = 0; r < 8; r++)
#pragma unroll
        for (int c = 0; c < 8; c++) acc[r][c] = 0.f;

    // Strided lane mapping: row = r*16+ty, col = c*16+tx.
    // A-reads broadcast across tx; B-reads hit 16 consecutive banks -> conflict-free.
#pragma unroll 4
    for (int k = 0; k < DIM; k++) {
        const float* Ak = As + k * 129;
        const float* Bk = Bs + k * 129;
        float a[8], b[8];
#pragma unroll
        for (int r = 0; r < 8; r++) a[r] = Ak[r * 16 + ty];
#pragma unroll
        for (int c = 0; c < 8; c++) b[c] = Bk[c * 16 + tx];
#pragma unroll
        for (int r = 0; r < 8; r++)
#pragma unroll
            for (int c = 0; c < 8; c++)
                acc[r][c] = fmaf(a[r], b[c], acc[r][c]);
    }

    // Epilogue: fused distance + masked hardest-pos/neg, per-row reduction.
#pragma unroll
    for (int r = 0; r < 8; r++) {
        const int   il = r * 16 + ty;
        const int   gi = ib + il;
        const float si = g_sq[gi];
        const int   li = labA[il];

        float pmax = 0.f;
        float nmin = 3.402823466e38f;
#pragma unroll
        for (int c = 0; c < 8; c++) {
            int   jl = c * 16 + tx;
            int   gj = jb + jl;
            float d2 = si + sqB[jl] - 2.f * acc[r][c];
            float dist = (d2 > 0.f) ? sqrtf(d2) : 0.f;
            if (li == labB[jl]) {
                if (gi != gj && dist > pmax) pmax = dist;
                // same-label neg candidate is dist+BIG; the global min is
                // always attained on a different-label entry (512 labels,
                // 8192 rows guarantees one exists), so skipping it is exact.
            } else {
                if (dist < nmin) nmin = dist;
            }
        }
        // reduce across the 16 tx lanes (xor offsets stay inside the half-warp)
#pragma unroll
        for (int off = 8; off; off >>= 1) {
            pmax = fmaxf(pmax, __shfl_xor_sync(0xffffffffu, pmax, off));
            nmin = fminf(nmin, __shfl_xor_sync(0xffffffffu, nmin, off));
        }
        if (tx == 0) {
            // nonneg floats: int-bit order == float order
            atomicMax(&g_pos[gi], __float_as_int(pmax));
            atomicMin(&g_neg[gi], __float_as_int(nmin));
        }
    }
}

// ---------------- finalize: mean relu(pos - neg + margin) ----------------
__global__ void finalize_kernel(const float* __restrict__ marginp,
                                float* __restrict__ out) {
    __shared__ float red[256];
    const float margin = *marginp;
    float s = 0.f;
    for (int i = threadIdx.x; i < NROWS; i += 256) {
        float pos = __int_as_float(g_pos[i]);
        float neg = __int_as_float(g_neg[i]);
        float l = pos - neg + margin;
        s += (l > 0.f) ? l : 0.f;
    }
    red[threadIdx.x] = s;
    __syncthreads();
    for (int o = 128; o; o >>= 1) {
        if (threadIdx.x < o) red[threadIdx.x] += red[threadIdx.x + o];
        __syncthreads();
    }
    if (threadIdx.x == 0) out[0] = red[0] / (float)NROWS;
}

// ---------------- launch ----------------
extern "C" void kernel_launch(void* const* d_in, const int* in_sizes, int n_in,
                              void* d_out, int out_size) {
    const float* X      = (const float*)d_in[0];
    const int*   labels = (const int*)d_in[1];
    const float* margin = (const float*)d_in[2];
    float*       out    = (float*)d_out;

    prep_kernel<<<NROWS / 256, 256>>>(X);

    size_t smem = 2 * 128 * 129 * sizeof(float);   // 132096 B dynamic
    cudaFuncSetAttribute(tile_kernel,
                         cudaFuncAttributeMaxDynamicSharedMemorySize,
                         (int)smem);
    dim3 grid(NROWS / BT, NROWS / BT);
    tile_kernel<<<grid, THREADS, smem>>>(X, labels);

    finalize_kernel<<<1, 256>>>(margin, out);
}

// round 7
// speedup vs baseline: 1.9160x; 1.9160x over previous
#include <cuda_runtime.h>

#define NROWS 8192
#define DIM   128
#define BT    128          // output tile (BT x BT)
#define THREADS 256
#define NB    (NROWS / BT)             // 64 tile-rows
#define NTILES (NB * (NB + 1) / 2)     // 2080 upper-triangular tiles

#define AS_STRIDE 129
#define BS_STRIDE 130      // even: 8B-aligned rows for LDS.64

// ---------------- device scratch (no allocs allowed) ----------------
__device__ float g_sq[NROWS];
__device__ int   g_pos[NROWS];   // float bits, running max (hardest positive)
__device__ int   g_neg[NROWS];   // float bits, running min (hardest negative)

// ---------------- prep: squared norms + init reductions ----------------
__global__ void prep_kernel(const float* __restrict__ X) {
    int i = blockIdx.x * blockDim.x + threadIdx.x;
    if (i >= NROWS) return;
    const float4* row = (const float4*)(X + (size_t)i * DIM);
    float s = 0.f;
#pragma unroll
    for (int q = 0; q < DIM / 4; q++) {
        float4 v = row[q];
        s += v.x * v.x + v.y * v.y + v.z * v.z + v.w * v.w;
    }
    g_sq[i]  = s;
    g_pos[i] = 0;            // 0.0f
    g_neg[i] = 0x7F7FFFFF;   // FLT_MAX
}

// ---------------- main: symmetric tiles, f32x2-packed Gram ----------------
__global__ void __launch_bounds__(THREADS, 1)
tile_kernel(const float* __restrict__ X,
            const int* __restrict__ labels) {   // int32 (JAX x64 off)
    extern __shared__ float smem[];
    float* As = smem;                          // k-major: As[k*129 + i]
    float* Bs = smem + DIM * AS_STRIDE;        // k-major: Bs[k*130 + j]
    __shared__ int   labA[BT];
    __shared__ int   labB[BT];
    __shared__ float sqA[BT];
    __shared__ float sqB[BT];
    __shared__ float colbufP[16 * BT];
    __shared__ float colbufN[16 * BT];

    const int tid = threadIdx.x;
    const int tx  = tid & 15;
    const int ty  = tid >> 4;

    // map linear tile index -> upper-triangular (bi, bj), bi <= bj
    int bi = 0, rem = blockIdx.x;
    while (rem >= NB - bi) { rem -= NB - bi; bi++; }
    const int bj = bi + rem;
    const int ib = bi * BT;
    const int jb = bj * BT;
    const bool offdiag = (bi != bj);

    // Load tiles, transposing to k-major (coalesced 512B-row global reads).
    for (int t = tid; t < BT * (DIM / 4); t += THREADS) {
        int kq  = t & 31;          // float4 index along k
        int row = t >> 5;
        float4 va = *(const float4*)(X + (size_t)(ib + row) * DIM + kq * 4);
        float4 vb = *(const float4*)(X + (size_t)(jb + row) * DIM + kq * 4);
        int k0 = kq * 4;
        As[(k0 + 0) * AS_STRIDE + row] = va.x;
        As[(k0 + 1) * AS_STRIDE + row] = va.y;
        As[(k0 + 2) * AS_STRIDE + row] = va.z;
        As[(k0 + 3) * AS_STRIDE + row] = va.w;
        Bs[(k0 + 0) * BS_STRIDE + row] = vb.x;
        Bs[(k0 + 1) * BS_STRIDE + row] = vb.y;
        Bs[(k0 + 2) * BS_STRIDE + row] = vb.z;
        Bs[(k0 + 3) * BS_STRIDE + row] = vb.w;
    }
    if (tid < BT) {
        labA[tid] = labels[ib + tid];
        labB[tid] = labels[jb + tid];
        sqA[tid]  = g_sq[ib + tid];
        sqB[tid]  = g_sq[jb + tid];
    }
    __syncthreads();

    // acc2[r][c2] holds two f32 accumulators: cols (c2*32 + 2*tx) and +1
    unsigned long long acc2[8][4];
#pragma unroll
    for (int r = 0; r < 8; r++)
#pragma unroll
        for (int c = 0; c < 4; c++) acc2[r][c] = 0ull;   // two +0.0f

#pragma unroll 4
    for (int k = 0; k < DIM; k++) {
        const float* Ak = As + k * AS_STRIDE;
        const float* Bk = Bs + k * BS_STRIDE;
        unsigned long long b2[4];
#pragma unroll
        for (int c = 0; c < 4; c++)   // LDS.64, 16 lanes x 8B contiguous: conflict-free
            b2[c] = *(const unsigned long long*)(Bk + c * 32 + tx * 2);
#pragma unroll
        for (int r = 0; r < 8; r++) {
            float a = Ak[r * 16 + ty];            // broadcast across tx
            unsigned long long ad;
            asm("mov.b64 %0, {%1, %1};" : "=l"(ad) : "f"(a));
#pragma unroll
            for (int c = 0; c < 4; c++)
                asm("fma.rn.f32x2 %0, %1, %2, %0;"
                    : "+l"(acc2[r][c]) : "l"(ad), "l"(b2[c]));
        }
    }

    // ---- epilogue: dist + hardest-pos/neg for rows (and cols if offdiag) ----
    float colP[8], colN[8];
#pragma unroll
    for (int q = 0; q < 8; q++) { colP[q] = 0.f; colN[q] = 3.402823466e38f; }

#pragma unroll
    for (int r = 0; r < 8; r++) {
        const int   il = r * 16 + ty;
        const int   gi = ib + il;
        const float si = sqA[il];
        const int   li = labA[il];

        float pmax = 0.f;
        float nmin = 3.402823466e38f;
#pragma unroll
        for (int c = 0; c < 4; c++) {
            uint2 u = *reinterpret_cast<uint2*>(&acc2[r][c]);
#pragma unroll
            for (int h = 0; h < 2; h++) {
                int   jl  = c * 32 + tx * 2 + h;
                int   gj  = jb + jl;
                float dot = __uint_as_float(h ? u.y : u.x);
                float d2  = si + sqB[jl] - 2.f * dot;
                float dist = (d2 > 0.f) ? sqrtf(d2) : 0.f;
                int q = c * 2 + h;
                if (li == labB[jl]) {
                    if (gi != gj) {
                        if (dist > pmax)    pmax    = dist;
                        if (dist > colP[q]) colP[q] = dist;
                    }
                    // same-label negative candidate (dist+BIG) can never be
                    // the global min (512 labels over 8192 rows guarantees a
                    // different-label entry per row) -> skipping is exact.
                } else {
                    if (dist < nmin)    nmin    = dist;
                    if (dist < colN[q]) colN[q] = dist;
                }
            }
        }
        // row reduce across 16 tx lanes (xor stays inside the half-warp)
#pragma unroll
        for (int off = 8; off; off >>= 1) {
            pmax = fmaxf(pmax, __shfl_xor_sync(0xffffffffu, pmax, off));
            nmin = fminf(nmin, __shfl_xor_sync(0xffffffffu, nmin, off));
        }
        if (tx == 0) {   // nonneg floats: int-bit order == float order
            atomicMax(&g_pos[gi], __float_as_int(pmax));
            atomicMin(&g_neg[gi], __float_as_int(nmin));
        }
    }

    // column side (transpose contribution) — only for off-diagonal tiles;
    // a diagonal tile is symmetric so the row pass already covered it.
    if (offdiag) {
#pragma unroll
        for (int c = 0; c < 4; c++)
#pragma unroll
            for (int h = 0; h < 2; h++) {
                int jl = c * 32 + tx * 2 + h;
                colbufP[ty * BT + jl] = colP[c * 2 + h];
                colbufN[ty * BT + jl] = colN[c * 2 + h];
            }
        __syncthreads();
        if (tid < BT) {
            float p = 0.f, nmv = 3.402823466e38f;
#pragma unroll
            for (int t = 0; t < 16; t++) {
                p   = fmaxf(p,   colbufP[t * BT + tid]);
                nmv = fminf(nmv, colbufN[t * BT + tid]);
            }
            atomicMax(&g_pos[jb + tid], __float_as_int(p));
            atomicMin(&g_neg[jb + tid], __float_as_int(nmv));
        }
    }
}

// ---------------- finalize: mean relu(pos - neg + margin) ----------------
__global__ void finalize_kernel(const float* __restrict__ marginp,
                                float* __restrict__ out) {
    __shared__ float red[256];
    const float margin = *marginp;
    float s = 0.f;
    for (int i = threadIdx.x; i < NROWS; i += 256) {
        float pos = __int_as_float(g_pos[i]);
        float neg = __int_as_float(g_neg[i]);
        float l = pos - neg + margin;
        s += (l > 0.f) ? l : 0.f;
    }
    red[threadIdx.x] = s;
    __syncthreads();
    for (int o = 128; o; o >>= 1) {
        if (threadIdx.x < o) red[threadIdx.x] += red[threadIdx.x + o];
        __syncthreads();
    }
    if (threadIdx.x == 0) out[0] = red[0] / (float)NROWS;
}

// ---------------- launch ----------------
extern "C" void kernel_launch(void* const* d_in, const int* in_sizes, int n_in,
                              void* d_out, int out_size) {
    const float* X      = (const float*)d_in[0];
    const int*   labels = (const int*)d_in[1];
    const float* margin = (const float*)d_in[2];
    float*       out    = (float*)d_out;

    prep_kernel<<<NROWS / 256, 256>>>(X);

    size_t smem = (size_t)DIM * (AS_STRIDE + BS_STRIDE) * sizeof(float); // 132608 B
    cudaFuncSetAttribute(tile_kernel,
                         cudaFuncAttributeMaxDynamicSharedMemorySize,
                         (int)smem);
    tile_kernel<<<NTILES, THREADS, smem>>>(X, labels);

    finalize_kernel<<<1, 256>>>(margin, out);
}